// round 13
// baseline (speedup 1.0000x reference)
#include <cuda_runtime.h>
#include <cuda_fp16.h>
#include <stdint.h>
#include <math.h>

#define B_  2
#define L_  2048
#define D_  1024
#define H_  16
#define E_  64
#define W_  256
#define NT  (B_*L_)   // 4096 tokens
#define N3  (3*D_)    // 3072

// Scratch (no allocations allowed) — fp16 2-term scheme
__device__ __half g_xh [NT * D_],  g_xl [NT * D_];
__device__ __half g_wqh[N3 * D_];
__device__ __half g_wph[D_ * D_];
__device__ __half g_qvh[NT * N3], g_qvl[NT * N3];   // qkv hi/lo
__device__ __half g_ath[NT * D_], g_atl[NT * D_];

// ===========================================================================
// Helpers
// ===========================================================================
__device__ __forceinline__ uint32_t smem_u32(const void* p) {
    uint32_t a;
    asm("{ .reg .u64 t; cvta.to.shared.u64 t, %1; cvt.u32.u64 %0, t; }"
        : "=r"(a) : "l"(p));
    return a;
}
__device__ __forceinline__ uint32_t pack_h2(__half a, __half b) {
    __half2 t = __halves2half2(a, b);
    return *(uint32_t*)&t;
}
__device__ __forceinline__ uint32_t pack_split_hi(float x, float y) {
    return pack_h2(__float2half_rn(x), __float2half_rn(y));
}
__device__ __forceinline__ uint32_t pack_split_lo(float x, float y) {
    __half hx = __float2half_rn(x), hy = __float2half_rn(y);
    return pack_h2(__float2half_rn(x - __half2float(hx)),
                   __float2half_rn(y - __half2float(hy)));
}
__device__ __forceinline__ void ldsm_x4(uint32_t* r, uint32_t addr) {
    asm volatile("ldmatrix.sync.aligned.m8n8.x4.shared.b16 {%0,%1,%2,%3}, [%4];"
                 : "=r"(r[0]), "=r"(r[1]), "=r"(r[2]), "=r"(r[3]) : "r"(addr));
}
__device__ __forceinline__ void ldsm_x4_t(uint32_t* r, uint32_t addr) {
    asm volatile("ldmatrix.sync.aligned.m8n8.x4.trans.shared.b16 {%0,%1,%2,%3}, [%4];"
                 : "=r"(r[0]), "=r"(r[1]), "=r"(r[2]), "=r"(r[3]) : "r"(addr));
}
__device__ __forceinline__ void mma16816(float* d, const uint32_t* a, const uint32_t* b) {
    asm volatile(
        "mma.sync.aligned.m16n8k16.row.col.f32.f16.f16.f32 "
        "{%0,%1,%2,%3}, {%4,%5,%6,%7}, {%8,%9}, {%0,%1,%2,%3};"
        : "+f"(d[0]), "+f"(d[1]), "+f"(d[2]), "+f"(d[3])
        : "r"(a[0]), "r"(a[1]), "r"(a[2]), "r"(a[3]), "r"(b[0]), "r"(b[1]));
}
#define CP_ASYNC16(dst, src) \
    asm volatile("cp.async.cg.shared.global [%0], [%1], 16;" :: "r"(dst), "l"(src))
#define CP_COMMIT() asm volatile("cp.async.commit_group;" ::: "memory")
#define CP_WAIT(n)  asm volatile("cp.async.wait_group %0;" :: "n"(n) : "memory")

// ===========================================================================
// Pre-passes: fp32 -> fp16 hi/lo split (x) and fp32 -> fp16 round (weights)
// ===========================================================================
__global__ __launch_bounds__(256) void split_kernel(
    const float* __restrict__ src, __half* __restrict__ hi,
    __half* __restrict__ lo, int n4)
{
    int i = blockIdx.x * 256 + threadIdx.x;
    if (i >= n4) return;
    float4 v = *(const float4*)&src[i * 4];
    uint2 hv = { pack_split_hi(v.x, v.y), pack_split_hi(v.z, v.w) };
    uint2 lv = { pack_split_lo(v.x, v.y), pack_split_lo(v.z, v.w) };
    *(uint2*)&hi[i * 4] = hv;
    *(uint2*)&lo[i * 4] = lv;
}
__global__ __launch_bounds__(256) void round_kernel(
    const float* __restrict__ src, __half* __restrict__ hi, int n4)
{
    int i = blockIdx.x * 256 + threadIdx.x;
    if (i >= n4) return;
    float4 v = *(const float4*)&src[i * 4];
    uint2 hv = { pack_split_hi(v.x, v.y), pack_split_hi(v.z, v.w) };
    *(uint2*)&hi[i * 4] = hv;
}

// ===========================================================================
// fp16 2-term HMMA GEMM (R9-proven 2-stage pipeline, BK=32):
// C = (Ah+Al)@Wh^T + bias   (W pre-rounded to fp16; error ~2^-12)
// CTA 128x128, 256 thr, warp tile 64x32, smem pitch 80B, 3 tiles/stage.
// SPLIT=true: write C as fp16 hi/lo pair instead of fp32.
// ===========================================================================
#define PITCH    80
#define TILE_B   (128 * PITCH)     // 10240
#define STAGE_B  (3 * TILE_B)      // 30720
#define SMEM_DYN (2 * STAGE_B)     // 61440

template<bool SPLIT>
__global__ __launch_bounds__(256) void gemm_tc(
    const __half* __restrict__ Ah, const __half* __restrict__ Al,
    const __half* __restrict__ Wh,
    const float* __restrict__ bias, float* __restrict__ C,
    __half* __restrict__ Ch, __half* __restrict__ Cl,
    int M, int N, int K)
{
    extern __shared__ char sm[];

    const int tid  = threadIdx.x;
    const int lane = tid & 31;
    const int wid  = tid >> 5;
    const int wm   = wid >> 2;
    const int wn   = wid & 3;
    const int n0   = blockIdx.x * 128;
    const int m0   = blockIdx.y * 128;

    const int rowA0 = tid >> 2;              // 0..63
    const int chA   = tid & 3;               // 16B chunk id

    float acc[4][4][4];
    #pragma unroll
    for (int i = 0; i < 4; i++)
        #pragma unroll
        for (int j = 0; j < 4; j++)
            #pragma unroll
            for (int r = 0; r < 4; r++) acc[i][j][r] = 0.f;

    const int KT = K / 32;

    auto issue = [&](int s, int k0) {
        uint32_t base = smem_u32(sm + s * STAGE_B);
        #pragma unroll
        for (int t = 0; t < 2; t++) {
            int row  = rowA0 + t * 64;
            uint32_t doff = (uint32_t)(row * PITCH + chA * 16);
            const __half* pa = Ah + (size_t)(m0 + row) * K + k0 + chA * 8;
            const __half* pl = Al + (size_t)(m0 + row) * K + k0 + chA * 8;
            const __half* pw = Wh + (size_t)(n0 + row) * K + k0 + chA * 8;
            CP_ASYNC16(base + doff,              pa);
            CP_ASYNC16(base + TILE_B + doff,     pl);
            CP_ASYNC16(base + 2 * TILE_B + doff, pw);
        }
        CP_COMMIT();
    };

    issue(0, 0);

    for (int it = 0; it < KT; it++) {
        const int s = it & 1;

        if (it + 1 < KT) { issue(s ^ 1, (it + 1) * 32); CP_WAIT(1); }
        else             { CP_WAIT(0); }
        __syncthreads();

        const uint32_t bAh = smem_u32(sm + s * STAGE_B);
        const uint32_t bAl = bAh + TILE_B;
        const uint32_t bWh = bAh + 2 * TILE_B;

        #pragma unroll
        for (int ks = 0; ks < 2; ks++) {
            uint32_t ah[4][4], al[4][4], bh[4][2];

            const uint32_t aoff0 = (uint32_t)(wm * 64 + (lane & 15)) * PITCH
                                 + (uint32_t)((lane >> 4) * 16 + ks * 32);
            #pragma unroll
            for (int mi = 0; mi < 4; mi++) {
                uint32_t off = aoff0 + (uint32_t)(mi * 16 * PITCH);
                ldsm_x4(ah[mi], bAh + off);
                ldsm_x4(al[mi], bAl + off);
            }

            const int mat = lane >> 3;
            const uint32_t boff0 = (uint32_t)(wn * 32 + ((mat >> 1) << 3) + (lane & 7)) * PITCH
                                 + (uint32_t)(((mat & 1) << 4) + ks * 32);
            #pragma unroll
            for (int nb = 0; nb < 2; nb++) {
                uint32_t t4[4];
                uint32_t off = boff0 + (uint32_t)(nb * 16 * PITCH);
                ldsm_x4(t4, bWh + off);
                bh[nb*2][0] = t4[0]; bh[nb*2][1] = t4[1];
                bh[nb*2+1][0] = t4[2]; bh[nb*2+1][1] = t4[3];
            }

            #pragma unroll
            for (int mi = 0; mi < 4; mi++)
                #pragma unroll
                for (int nj = 0; nj < 4; nj++) {
                    mma16816(acc[mi][nj], ah[mi], bh[nj]);
                    mma16816(acc[mi][nj], al[mi], bh[nj]);
                }
        }
        __syncthreads();   // all reads of this stage done before it is re-filled
    }

    // ---- epilogue ----
    #pragma unroll
    for (int mi = 0; mi < 4; mi++) {
        int r0 = m0 + wm * 64 + mi * 16 + (lane >> 2);
        #pragma unroll
        for (int nj = 0; nj < 4; nj++) {
            int col = n0 + wn * 32 + nj * 8 + (lane & 3) * 2;
            float2 bb = *(const float2*)&bias[col];
            float v00 = acc[mi][nj][0] + bb.x, v01 = acc[mi][nj][1] + bb.y;
            float v10 = acc[mi][nj][2] + bb.x, v11 = acc[mi][nj][3] + bb.y;
            if (SPLIT) {
                size_t o0 = (size_t)r0 * N + col, o1 = (size_t)(r0 + 8) * N + col;
                *(uint32_t*)&Ch[o0] = pack_split_hi(v00, v01);
                *(uint32_t*)&Cl[o0] = pack_split_lo(v00, v01);
                *(uint32_t*)&Ch[o1] = pack_split_hi(v10, v11);
                *(uint32_t*)&Cl[o1] = pack_split_lo(v10, v11);
            } else {
                float2 a = { v00, v01 }, b2 = { v10, v11 };
                *(float2*)&C[(size_t)r0 * N + col]       = a;
                *(float2*)&C[(size_t)(r0 + 8) * N + col] = b2;
            }
        }
    }
}

// ===========================================================================
// Tensor-core sliding-window flash attention, fp16 2-term.
// S = (Qh+Ql)·Kh^T ; O += (Ph+Pl)·Vh   (K, V rounded fp16)
// Block = (b, h, 64-query tile), 128 threads, warp = 16 query rows.
// smem: Qh,Ql + 2-stage {Kh,Vh}, pitch 144B, cp.async pipelined.
// ===========================================================================
#define APITCH 144
#define ATILE  (64 * APITCH)       // 9216
#define ASTAGE (2 * ATILE)         // 18432
#define ASMEM  (2 * ATILE + 2 * ASTAGE)   // 55296

__global__ __launch_bounds__(128) void attn_tc(
    const __half* __restrict__ qvh, const __half* __restrict__ qvl,
    __half* __restrict__ ath, __half* __restrict__ atl)
{
    extern __shared__ char sm[];
    const int q0   = blockIdx.x * 64;
    const int h    = blockIdx.y;
    const int b    = blockIdx.z;
    const int tid  = threadIdx.x;
    const int lane = tid & 31;
    const int wid  = tid >> 5;
    const int hoff = h * E_;
    const uint32_t base = smem_u32(sm);

    auto issueKV = [&](int slot, int c) {
        uint32_t sb = base + 2 * ATILE + slot * ASTAGE;
        #pragma unroll
        for (int t = 0; t < 4; t++) {
            int idx = tid + t * 128;
            int r   = idx >> 3;
            int ch  = idx & 7;
            size_t g = (size_t)(b * L_ + c + r) * N3 + hoff + ch * 8;
            uint32_t doff = (uint32_t)(r * APITCH + ch * 16);
            CP_ASYNC16(sb + doff,         qvh + g + D_);        // Kh
            CP_ASYNC16(sb + ATILE + doff, qvh + g + 2 * D_);    // Vh
        }
        CP_COMMIT();
    };

    // Q hi/lo load (joins issueKV(0)'s commit group)
    #pragma unroll
    for (int t = 0; t < 4; t++) {
        int idx = tid + t * 128;
        int r   = idx >> 3;
        int ch  = idx & 7;
        size_t g = (size_t)(b * L_ + q0 + r) * N3 + hoff + ch * 8;
        uint32_t doff = (uint32_t)(r * APITCH + ch * 16);
        CP_ASYNC16(base + doff,         qvh + g);
        CP_ASYNC16(base + ATILE + doff, qvl + g);
    }

    const int cbeg = (q0 >= W_) ? (q0 - W_) : 0;
    const int nch  = (q0 - cbeg) / 64 + 1;

    issueKV(0, cbeg);
    if (nch > 1) issueKV(1, cbeg + 64);

    float m0 = -1e30f, m1 = -1e30f, l0 = 0.f, l1 = 0.f;
    float o[8][4];
    #pragma unroll
    for (int i = 0; i < 8; i++)
        #pragma unroll
        for (int j = 0; j < 4; j++) o[i][j] = 0.f;

    const int gr0 = q0 + wid * 16 + (lane >> 2);
    const int gr1 = gr0 + 8;

    for (int ci = 0; ci < nch; ci++) {
        const int c = cbeg + ci * 64;
        if (ci + 1 < nch) { CP_WAIT(1); } else { CP_WAIT(0); }
        __syncthreads();

        const uint32_t sb  = base + 2 * ATILE + (ci & 1) * ASTAGE;
        const uint32_t bKh = sb;
        const uint32_t bVh = sb + ATILE;

        // ---- S = Q K^T (2-term) ----
        float s[8][4];
        #pragma unroll
        for (int i = 0; i < 8; i++)
            #pragma unroll
            for (int j = 0; j < 4; j++) s[i][j] = 0.f;

        const int mat = lane >> 3;
        #pragma unroll
        for (int ks = 0; ks < 4; ks++) {
            uint32_t qh4[4], ql4[4];
            uint32_t aoff = (uint32_t)(wid * 16 + (lane & 15)) * APITCH
                          + (uint32_t)(((lane >> 4) << 4) + ks * 32);
            ldsm_x4(qh4, base + aoff);
            ldsm_x4(ql4, base + ATILE + aoff);
            #pragma unroll
            for (int np = 0; np < 4; np++) {
                uint32_t kh[4];
                uint32_t boff = (uint32_t)(np * 16 + ((mat >> 1) << 3) + (lane & 7)) * APITCH
                              + (uint32_t)(((mat & 1) << 4) + ks * 32);
                ldsm_x4(kh, bKh + boff);
                mma16816(s[np*2],   qh4, &kh[0]);
                mma16816(s[np*2],   ql4, &kh[0]);
                mma16816(s[np*2+1], qh4, &kh[2]);
                mma16816(s[np*2+1], ql4, &kh[2]);
            }
        }

        // ---- scale + mask + online softmax ----
        const bool need_mask = (c == q0) || (c == cbeg && q0 >= W_);
        float rm0 = -1e30f, rm1 = -1e30f;
        #pragma unroll
        for (int nb = 0; nb < 8; nb++) {
            #pragma unroll
            for (int cc = 0; cc < 4; cc++) {
                float v = s[nb][cc] * 0.125f;
                if (need_mask) {
                    int i = (cc < 2) ? gr0 : gr1;
                    int j = c + nb * 8 + (lane & 3) * 2 + (cc & 1);
                    if (!(j <= i && i - j < W_)) v = -1e30f;
                }
                s[nb][cc] = v;
            }
            rm0 = fmaxf(rm0, fmaxf(s[nb][0], s[nb][1]));
            rm1 = fmaxf(rm1, fmaxf(s[nb][2], s[nb][3]));
        }
        rm0 = fmaxf(rm0, __shfl_xor_sync(0xffffffffu, rm0, 1));
        rm0 = fmaxf(rm0, __shfl_xor_sync(0xffffffffu, rm0, 2));
        rm1 = fmaxf(rm1, __shfl_xor_sync(0xffffffffu, rm1, 1));
        rm1 = fmaxf(rm1, __shfl_xor_sync(0xffffffffu, rm1, 2));

        float mn0 = fmaxf(m0, rm0), mn1 = fmaxf(m1, rm1);
        float corr0 = __expf(m0 - mn0), corr1 = __expf(m1 - mn1);
        float rs0 = 0.f, rs1 = 0.f;
        #pragma unroll
        for (int nb = 0; nb < 8; nb++) {
            float p0 = __expf(s[nb][0] - mn0);
            float p1 = __expf(s[nb][1] - mn0);
            float p2 = __expf(s[nb][2] - mn1);
            float p3 = __expf(s[nb][3] - mn1);
            s[nb][0] = p0; s[nb][1] = p1; s[nb][2] = p2; s[nb][3] = p3;
            rs0 += p0 + p1; rs1 += p2 + p3;
        }
        rs0 += __shfl_xor_sync(0xffffffffu, rs0, 1);
        rs0 += __shfl_xor_sync(0xffffffffu, rs0, 2);
        rs1 += __shfl_xor_sync(0xffffffffu, rs1, 1);
        rs1 += __shfl_xor_sync(0xffffffffu, rs1, 2);
        l0 = l0 * corr0 + rs0;  l1 = l1 * corr1 + rs1;
        m0 = mn0;  m1 = mn1;
        #pragma unroll
        for (int nb = 0; nb < 8; nb++) {
            o[nb][0] *= corr0; o[nb][1] *= corr0;
            o[nb][2] *= corr1; o[nb][3] *= corr1;
        }

        // ---- O += P V (2-term; P split hi/lo in registers) ----
        #pragma unroll
        for (int kj = 0; kj < 4; kj++) {
            uint32_t pah[4], pal[4];
            pah[0] = pack_split_hi(s[2*kj][0],   s[2*kj][1]);
            pal[0] = pack_split_lo(s[2*kj][0],   s[2*kj][1]);
            pah[1] = pack_split_hi(s[2*kj][2],   s[2*kj][3]);
            pal[1] = pack_split_lo(s[2*kj][2],   s[2*kj][3]);
            pah[2] = pack_split_hi(s[2*kj+1][0], s[2*kj+1][1]);
            pal[2] = pack_split_lo(s[2*kj+1][0], s[2*kj+1][1]);
            pah[3] = pack_split_hi(s[2*kj+1][2], s[2*kj+1][3]);
            pal[3] = pack_split_lo(s[2*kj+1][2], s[2*kj+1][3]);

            #pragma unroll
            for (int ep = 0; ep < 4; ep++) {
                uint32_t vh[4];
                uint32_t voff = (uint32_t)(kj * 16 + ((mat & 1) << 3) + (lane & 7)) * APITCH
                              + (uint32_t)(((mat >> 1) << 4) + ep * 32);
                ldsm_x4_t(vh, bVh + voff);
                mma16816(o[ep*2],   pah, &vh[0]);
                mma16816(o[ep*2],   pal, &vh[0]);
                mma16816(o[ep*2+1], pah, &vh[2]);
                mma16816(o[ep*2+1], pal, &vh[2]);
            }
        }

        if (ci + 2 < nch) {
            __syncthreads();            // all warps done reading slot ci&1
            issueKV(ci & 1, c + 128);
        }
    }

    // ---- normalize + split-store ----
    const float inv0 = 1.0f / l0, inv1 = 1.0f / l1;
    const size_t ob0 = (size_t)(b * L_ + gr0) * D_ + hoff;
    const size_t ob1 = (size_t)(b * L_ + gr1) * D_ + hoff;
    #pragma unroll
    for (int nb = 0; nb < 8; nb++) {
        int e = nb * 8 + (lane & 3) * 2;
        float v00 = o[nb][0] * inv0, v01 = o[nb][1] * inv0;
        float v10 = o[nb][2] * inv1, v11 = o[nb][3] * inv1;
        *(uint32_t*)&ath[ob0 + e] = pack_split_hi(v00, v01);
        *(uint32_t*)&atl[ob0 + e] = pack_split_lo(v00, v01);
        *(uint32_t*)&ath[ob1 + e] = pack_split_hi(v10, v11);
        *(uint32_t*)&atl[ob1 + e] = pack_split_lo(v10, v11);
    }
}

// ---------------------------------------------------------------------------
extern "C" void kernel_launch(void* const* d_in, const int* in_sizes, int n_in,
                              void* d_out, int out_size)
{
    const float* x      = (const float*)d_in[0];
    const float* w_qkv  = (const float*)d_in[1];
    const float* b_qkv  = (const float*)d_in[2];
    const float* w_proj = (const float*)d_in[3];
    const float* b_proj = (const float*)d_in[4];
    float* out = (float*)d_out;

    __half *xh, *xl, *wqh, *wph, *qvh, *qvl, *ath, *atl;
    cudaGetSymbolAddress((void**)&xh,  g_xh);  cudaGetSymbolAddress((void**)&xl,  g_xl);
    cudaGetSymbolAddress((void**)&wqh, g_wqh);
    cudaGetSymbolAddress((void**)&wph, g_wph);
    cudaGetSymbolAddress((void**)&qvh, g_qvh); cudaGetSymbolAddress((void**)&qvl, g_qvl);
    cudaGetSymbolAddress((void**)&ath, g_ath); cudaGetSymbolAddress((void**)&atl, g_atl);

    cudaFuncSetAttribute(gemm_tc<true>,  cudaFuncAttributeMaxDynamicSharedMemorySize, SMEM_DYN);
    cudaFuncSetAttribute(gemm_tc<false>, cudaFuncAttributeMaxDynamicSharedMemorySize, SMEM_DYN);
    cudaFuncSetAttribute(attn_tc, cudaFuncAttributeMaxDynamicSharedMemorySize, ASMEM);

    // 0) pre-passes: x -> fp16 hi/lo; weights -> fp16 (rounded)
    split_kernel<<<(NT*D_/4 + 255)/256, 256>>>(x,      xh,  xl,  NT*D_/4);
    round_kernel<<<(N3*D_/4 + 255)/256, 256>>>(w_qkv,  wqh, N3*D_/4);
    round_kernel<<<(D_*D_/4 + 255)/256, 256>>>(w_proj, wph, D_*D_/4);

    // 1) qkv = x @ w_qkv^T + b_qkv  -> fp16 hi/lo   [4096, 3072]
    gemm_tc<true><<<dim3(N3 / 128, NT / 128), 256, SMEM_DYN>>>(
        xh, xl, wqh, b_qkv, nullptr, qvh, qvl, NT, N3, D_);

    // 2) tensor-core sliding-window attention -> fp16 hi/lo  [4096, 1024]
    attn_tc<<<dim3(L_ / 64, H_, B_), 128, ASMEM>>>(qvh, qvl, ath, atl);

    // 3) out = att @ w_proj^T + b_proj   [4096, 1024] fp32
    gemm_tc<false><<<dim3(D_ / 128, NT / 128), 256, SMEM_DYN>>>(
        ath, atl, wph, b_proj, out, nullptr, nullptr, NT, D_, D_);
}

// round 14
// speedup vs baseline: 1.2484x; 1.2484x over previous
#include <cuda_runtime.h>
#include <cuda_bf16.h>
#include <stdint.h>
#include <math.h>

#define B_  2
#define L_  2048
#define D_  1024
#define H_  16
#define E_  64
#define W_  256
#define NT  (B_*L_)   // 4096 tokens
#define N3  (3*D_)    // 3072

// Scratch (no allocations allowed)
__device__ __nv_bfloat16 g_xh [NT * D_],  g_xl [NT * D_];
__device__ __nv_bfloat16 g_wqh[N3 * D_],  g_wql[N3 * D_];
__device__ __nv_bfloat16 g_wph[D_ * D_],  g_wpl[D_ * D_];
__device__ __nv_bfloat16 g_qvh[NT * N3],  g_qvl[NT * N3];   // qkv hi/lo
__device__ __nv_bfloat16 g_ath[NT * D_],  g_atl[NT * D_];

// ===========================================================================
// Helpers
// ===========================================================================
__device__ __forceinline__ uint32_t smem_u32(const void* p) {
    uint32_t a;
    asm("{ .reg .u64 t; cvta.to.shared.u64 t, %1; cvt.u32.u64 %0, t; }"
        : "=r"(a) : "l"(p));
    return a;
}
__device__ __forceinline__ uint32_t pack_bf16x2(__nv_bfloat16 a, __nv_bfloat16 b) {
    __nv_bfloat162 t = __halves2bfloat162(a, b);
    return *(uint32_t*)&t;
}
__device__ __forceinline__ uint32_t pack_split_hi(float x, float y) {
    return pack_bf16x2(__float2bfloat16_rn(x), __float2bfloat16_rn(y));
}
__device__ __forceinline__ uint32_t pack_split_lo(float x, float y) {
    __nv_bfloat16 hx = __float2bfloat16_rn(x), hy = __float2bfloat16_rn(y);
    return pack_bf16x2(__float2bfloat16_rn(x - __bfloat162float(hx)),
                       __float2bfloat16_rn(y - __bfloat162float(hy)));
}
__device__ __forceinline__ void ldsm_x4(uint32_t* r, uint32_t addr) {
    asm volatile("ldmatrix.sync.aligned.m8n8.x4.shared.b16 {%0,%1,%2,%3}, [%4];"
                 : "=r"(r[0]), "=r"(r[1]), "=r"(r[2]), "=r"(r[3]) : "r"(addr));
}
__device__ __forceinline__ void ldsm_x4_t(uint32_t* r, uint32_t addr) {
    asm volatile("ldmatrix.sync.aligned.m8n8.x4.trans.shared.b16 {%0,%1,%2,%3}, [%4];"
                 : "=r"(r[0]), "=r"(r[1]), "=r"(r[2]), "=r"(r[3]) : "r"(addr));
}
__device__ __forceinline__ void mma16816(float* d, const uint32_t* a, const uint32_t* b) {
    asm volatile(
        "mma.sync.aligned.m16n8k16.row.col.f32.bf16.bf16.f32 "
        "{%0,%1,%2,%3}, {%4,%5,%6,%7}, {%8,%9}, {%0,%1,%2,%3};"
        : "+f"(d[0]), "+f"(d[1]), "+f"(d[2]), "+f"(d[3])
        : "r"(a[0]), "r"(a[1]), "r"(a[2]), "r"(a[3]), "r"(b[0]), "r"(b[1]));
}
#define CP_ASYNC16(dst, src) \
    asm volatile("cp.async.cg.shared.global [%0], [%1], 16;" :: "r"(dst), "l"(src))
#define CP_COMMIT() asm volatile("cp.async.commit_group;" ::: "memory")
#define CP_WAIT(n)  asm volatile("cp.async.wait_group %0;" :: "n"(n) : "memory")

// ===========================================================================
// Elementwise fp32 -> bf16 hi/lo split (one-time pre-pass for x, weights)
// ===========================================================================
__global__ __launch_bounds__(256) void split_kernel(
    const float* __restrict__ src, __nv_bfloat16* __restrict__ hi,
    __nv_bfloat16* __restrict__ lo, int n4)
{
    int i = blockIdx.x * 256 + threadIdx.x;
    if (i >= n4) return;
    float4 v = *(const float4*)&src[i * 4];
    uint2 hv = { pack_split_hi(v.x, v.y), pack_split_hi(v.z, v.w) };
    uint2 lv = { pack_split_lo(v.x, v.y), pack_split_lo(v.z, v.w) };
    *(uint2*)&hi[i * 4] = hv;
    *(uint2*)&lo[i * 4] = lv;
}

// ===========================================================================
// Split-bf16 HMMA GEMM, 3-stage cp.async, ONE barrier per BK=32 iteration.
// C = (Ah+Al)@(Wh+Wl)^T + bias ~ AhWh + AhWl + AlWh.
// CTA 128x128, 256 thr, warp tile 64x32. smem tiles: 128 rows x 64B, XOR
// swizzle (off ^= (row&6)<<3) => conflict-free ldsm with ZERO padding.
// 4 tiles x 8KB = 32KB/stage, 3 stages = 96KB -> 2 CTAs/SM.
// Slot reuse: issue distance 2; slot (it+2)%3 was read at iter it-1, and all
// warps passed this iter's barrier only after finishing it-1 => safe.
// SPLIT=true: write C as bf16 hi/lo pair instead of fp32.
// ===========================================================================
#define TILE_B   (128 * 64)        // 8192
#define STAGE_B  (4 * TILE_B)      // 32768
#define SMEM_DYN (3 * STAGE_B)     // 98304

template<bool SPLIT>
__global__ __launch_bounds__(256) void gemm_tc(
    const __nv_bfloat16* __restrict__ Ah, const __nv_bfloat16* __restrict__ Al,
    const __nv_bfloat16* __restrict__ Wh, const __nv_bfloat16* __restrict__ Wl,
    const float* __restrict__ bias, float* __restrict__ C,
    __nv_bfloat16* __restrict__ Ch, __nv_bfloat16* __restrict__ Cl,
    int M, int N, int K)
{
    extern __shared__ char sm[];

    const int tid  = threadIdx.x;
    const int lane = tid & 31;
    const int wid  = tid >> 5;
    const int wm   = wid >> 2;
    const int wn   = wid & 3;
    const int n0   = blockIdx.x * 128;
    const int m0   = blockIdx.y * 128;

    const int rowA0 = tid >> 2;              // 0..63
    const int chA   = tid & 3;               // 16B chunk id 0..3
    const uint32_t ldxor = (uint32_t)((rowA0 & 6) << 3);  // swizzle for loads

    float acc[4][4][4];
    #pragma unroll
    for (int i = 0; i < 4; i++)
        #pragma unroll
        for (int j = 0; j < 4; j++)
            #pragma unroll
            for (int r = 0; r < 4; r++) acc[i][j][r] = 0.f;

    const int KT = K / 32;

    auto issue = [&](int s, int k0) {
        uint32_t base = smem_u32(sm + s * STAGE_B);
        #pragma unroll
        for (int t = 0; t < 2; t++) {
            int row  = rowA0 + t * 64;       // row&6 invariant under +64
            uint32_t doff = ((uint32_t)(row * 64 + chA * 16)) ^ ldxor;
            const __nv_bfloat16* pa = Ah + (size_t)(m0 + row) * K + k0 + chA * 8;
            const __nv_bfloat16* pl = Al + (size_t)(m0 + row) * K + k0 + chA * 8;
            const __nv_bfloat16* ph = Wh + (size_t)(n0 + row) * K + k0 + chA * 8;
            const __nv_bfloat16* pw = Wl + (size_t)(n0 + row) * K + k0 + chA * 8;
            CP_ASYNC16(base + doff,              pa);
            CP_ASYNC16(base + TILE_B + doff,     pl);
            CP_ASYNC16(base + 2 * TILE_B + doff, ph);
            CP_ASYNC16(base + 3 * TILE_B + doff, pw);
        }
        CP_COMMIT();
    };

    issue(0, 0);
    issue(1, 32);

    const uint32_t mmxor = (uint32_t)((lane & 6) << 3);   // (row&6)<<3 for ldsm rows

    for (int it = 0; it < KT; it++) {
        if (it + 1 < KT) { CP_WAIT(1); } else { CP_WAIT(0); }
        __syncthreads();

        const int s = it % 3;
        const uint32_t bAh = smem_u32(sm + s * STAGE_B);
        const uint32_t bAl = bAh + TILE_B;
        const uint32_t bWh = bAh + 2 * TILE_B;
        const uint32_t bWl = bAh + 3 * TILE_B;

        #pragma unroll
        for (int ks = 0; ks < 2; ks++) {
            uint32_t ah[4][4], al[4][4], bh[4][2], bl[4][2];

            // A rows: wm*64 + (lane&15) + mi*16 ; col: (lane>>4)*16 + ks*32
            const uint32_t aoff0 = ((uint32_t)((wm * 64 + (lane & 15)) * 64
                                  + (lane >> 4) * 16 + ks * 32)) ^ mmxor;
            #pragma unroll
            for (int mi = 0; mi < 4; mi++) {
                uint32_t off = aoff0 + (uint32_t)(mi * 16 * 64);  // +16 rows, swizzle invariant
                ldsm_x4(ah[mi], bAh + off);
                ldsm_x4(al[mi], bAl + off);
            }

            // W rows: wn*32 + ((mat>>1)<<3) + (lane&7) ; col: (mat&1)*16 + ks*32
            const int mat = lane >> 3;
            const uint32_t boff0 = ((uint32_t)((wn * 32 + ((mat >> 1) << 3) + (lane & 7)) * 64
                                  + ((mat & 1) << 4) + ks * 32)) ^ mmxor;
            #pragma unroll
            for (int nb = 0; nb < 2; nb++) {
                uint32_t t4[4];
                uint32_t off = boff0 + (uint32_t)(nb * 16 * 64);
                ldsm_x4(t4, bWh + off);
                bh[nb*2][0] = t4[0]; bh[nb*2][1] = t4[1];
                bh[nb*2+1][0] = t4[2]; bh[nb*2+1][1] = t4[3];
                ldsm_x4(t4, bWl + off);
                bl[nb*2][0] = t4[0]; bl[nb*2][1] = t4[1];
                bl[nb*2+1][0] = t4[2]; bl[nb*2+1][1] = t4[3];
            }

            #pragma unroll
            for (int mi = 0; mi < 4; mi++)
                #pragma unroll
                for (int nj = 0; nj < 4; nj++) {
                    mma16816(acc[mi][nj], ah[mi], bh[nj]);
                    mma16816(acc[mi][nj], ah[mi], bl[nj]);
                    mma16816(acc[mi][nj], al[mi], bh[nj]);
                }
        }

        if (it + 2 < KT) issue((it + 2) % 3, (it + 2) * 32);
    }

    // ---- epilogue ----
    #pragma unroll
    for (int mi = 0; mi < 4; mi++) {
        int r0 = m0 + wm * 64 + mi * 16 + (lane >> 2);
        #pragma unroll
        for (int nj = 0; nj < 4; nj++) {
            int col = n0 + wn * 32 + nj * 8 + (lane & 3) * 2;
            float2 bb = *(const float2*)&bias[col];
            float v00 = acc[mi][nj][0] + bb.x, v01 = acc[mi][nj][1] + bb.y;
            float v10 = acc[mi][nj][2] + bb.x, v11 = acc[mi][nj][3] + bb.y;
            if (SPLIT) {
                size_t o0 = (size_t)r0 * N + col, o1 = (size_t)(r0 + 8) * N + col;
                *(uint32_t*)&Ch[o0] = pack_split_hi(v00, v01);
                *(uint32_t*)&Cl[o0] = pack_split_lo(v00, v01);
                *(uint32_t*)&Ch[o1] = pack_split_hi(v10, v11);
                *(uint32_t*)&Cl[o1] = pack_split_lo(v10, v11);
            } else {
                float2 a = { v00, v01 }, b2 = { v10, v11 };
                *(float2*)&C[(size_t)r0 * N + col]       = a;
                *(float2*)&C[(size_t)(r0 + 8) * N + col] = b2;
            }
        }
    }
}

// ===========================================================================
// Tensor-core sliding-window flash attention (R9-verified, bf16 3-term).
// Block = (b, h, 64-query tile), 128 threads (4 warps), warp = 16 query rows.
// qkv in pre-split bf16 hi/lo. S = QhKh+QhKl+QlKh; O += PhVh+PhVl+PlVh.
// ===========================================================================
#define APITCH 144
#define ATILE  (64 * APITCH)       // 9216
#define ASTAGE (4 * ATILE)         // 36864
#define ASMEM  (2 * ATILE + 2 * ASTAGE)   // 92160

__global__ __launch_bounds__(128) void attn_tc(
    const __nv_bfloat16* __restrict__ qvh, const __nv_bfloat16* __restrict__ qvl,
    __nv_bfloat16* __restrict__ ath, __nv_bfloat16* __restrict__ atl)
{
    extern __shared__ char sm[];
    const int q0   = blockIdx.x * 64;
    const int h    = blockIdx.y;
    const int b    = blockIdx.z;
    const int tid  = threadIdx.x;
    const int lane = tid & 31;
    const int wid  = tid >> 5;
    const int hoff = h * E_;
    const uint32_t base = smem_u32(sm);

    auto issueKV = [&](int slot, int c) {
        uint32_t sb = base + 2 * ATILE + slot * ASTAGE;
        #pragma unroll
        for (int t = 0; t < 4; t++) {
            int idx = tid + t * 128;
            int r   = idx >> 3;
            int ch  = idx & 7;
            size_t g = (size_t)(b * L_ + c + r) * N3 + hoff + ch * 8;
            uint32_t doff = (uint32_t)(r * APITCH + ch * 16);
            CP_ASYNC16(sb + doff,             qvh + g + D_);
            CP_ASYNC16(sb + ATILE + doff,     qvl + g + D_);
            CP_ASYNC16(sb + 2 * ATILE + doff, qvh + g + 2 * D_);
            CP_ASYNC16(sb + 3 * ATILE + doff, qvl + g + 2 * D_);
        }
        CP_COMMIT();
    };

    // Q hi/lo load (bundled into first commit group by issueKV's commit)
    #pragma unroll
    for (int t = 0; t < 4; t++) {
        int idx = tid + t * 128;
        int r   = idx >> 3;
        int ch  = idx & 7;
        size_t g = (size_t)(b * L_ + q0 + r) * N3 + hoff + ch * 8;
        uint32_t doff = (uint32_t)(r * APITCH + ch * 16);
        CP_ASYNC16(base + doff,         qvh + g);
        CP_ASYNC16(base + ATILE + doff, qvl + g);
    }

    const int cbeg = (q0 >= W_) ? (q0 - W_) : 0;
    const int nch  = (q0 - cbeg) / 64 + 1;

    issueKV(0, cbeg);
    if (nch > 1) issueKV(1, cbeg + 64);

    float m0 = -1e30f, m1 = -1e30f, l0 = 0.f, l1 = 0.f;
    float o[8][4];
    #pragma unroll
    for (int i = 0; i < 8; i++)
        #pragma unroll
        for (int j = 0; j < 4; j++) o[i][j] = 0.f;

    const int gr0 = q0 + wid * 16 + (lane >> 2);
    const int gr1 = gr0 + 8;

    for (int ci = 0; ci < nch; ci++) {
        const int c = cbeg + ci * 64;
        if (ci + 1 < nch) { CP_WAIT(1); } else { CP_WAIT(0); }
        __syncthreads();

        const uint32_t sb  = base + 2 * ATILE + (ci & 1) * ASTAGE;
        const uint32_t bKh = sb, bKl = sb + ATILE;
        const uint32_t bVh = sb + 2 * ATILE, bVl = sb + 3 * ATILE;

        // ---- S = Q K^T (3-term split) ----
        float s[8][4];
        #pragma unroll
        for (int i = 0; i < 8; i++)
            #pragma unroll
            for (int j = 0; j < 4; j++) s[i][j] = 0.f;

        const int mat = lane >> 3;
        #pragma unroll
        for (int ks = 0; ks < 4; ks++) {
            uint32_t qh4[4], ql4[4];
            uint32_t aoff = (uint32_t)(wid * 16 + (lane & 15)) * APITCH
                          + (uint32_t)(((lane >> 4) << 4) + ks * 32);
            ldsm_x4(qh4, base + aoff);
            ldsm_x4(ql4, base + ATILE + aoff);
            #pragma unroll
            for (int np = 0; np < 4; np++) {
                uint32_t kh[4], kl[4];
                uint32_t boff = (uint32_t)(np * 16 + ((mat >> 1) << 3) + (lane & 7)) * APITCH
                              + (uint32_t)(((mat & 1) << 4) + ks * 32);
                ldsm_x4(kh, bKh + boff);
                ldsm_x4(kl, bKl + boff);
                mma16816(s[np*2],   qh4, &kh[0]);
                mma16816(s[np*2],   qh4, &kl[0]);
                mma16816(s[np*2],   ql4, &kh[0]);
                mma16816(s[np*2+1], qh4, &kh[2]);
                mma16816(s[np*2+1], qh4, &kl[2]);
                mma16816(s[np*2+1], ql4, &kh[2]);
            }
        }

        // ---- scale + mask + online softmax ----
        const bool need_mask = (c == q0) || (c == cbeg && q0 >= W_);
        float rm0 = -1e30f, rm1 = -1e30f;
        #pragma unroll
        for (int nb = 0; nb < 8; nb++) {
            #pragma unroll
            for (int cc = 0; cc < 4; cc++) {
                float v = s[nb][cc] * 0.125f;
                if (need_mask) {
                    int i = (cc < 2) ? gr0 : gr1;
                    int j = c + nb * 8 + (lane & 3) * 2 + (cc & 1);
                    if (!(j <= i && i - j < W_)) v = -1e30f;
                }
                s[nb][cc] = v;
            }
            rm0 = fmaxf(rm0, fmaxf(s[nb][0], s[nb][1]));
            rm1 = fmaxf(rm1, fmaxf(s[nb][2], s[nb][3]));
        }
        rm0 = fmaxf(rm0, __shfl_xor_sync(0xffffffffu, rm0, 1));
        rm0 = fmaxf(rm0, __shfl_xor_sync(0xffffffffu, rm0, 2));
        rm1 = fmaxf(rm1, __shfl_xor_sync(0xffffffffu, rm1, 1));
        rm1 = fmaxf(rm1, __shfl_xor_sync(0xffffffffu, rm1, 2));

        float mn0 = fmaxf(m0, rm0), mn1 = fmaxf(m1, rm1);
        float corr0 = __expf(m0 - mn0), corr1 = __expf(m1 - mn1);
        float rs0 = 0.f, rs1 = 0.f;
        #pragma unroll
        for (int nb = 0; nb < 8; nb++) {
            float p0 = __expf(s[nb][0] - mn0);
            float p1 = __expf(s[nb][1] - mn0);
            float p2 = __expf(s[nb][2] - mn1);
            float p3 = __expf(s[nb][3] - mn1);
            s[nb][0] = p0; s[nb][1] = p1; s[nb][2] = p2; s[nb][3] = p3;
            rs0 += p0 + p1; rs1 += p2 + p3;
        }
        rs0 += __shfl_xor_sync(0xffffffffu, rs0, 1);
        rs0 += __shfl_xor_sync(0xffffffffu, rs0, 2);
        rs1 += __shfl_xor_sync(0xffffffffu, rs1, 1);
        rs1 += __shfl_xor_sync(0xffffffffu, rs1, 2);
        l0 = l0 * corr0 + rs0;  l1 = l1 * corr1 + rs1;
        m0 = mn0;  m1 = mn1;
        #pragma unroll
        for (int nb = 0; nb < 8; nb++) {
            o[nb][0] *= corr0; o[nb][1] *= corr0;
            o[nb][2] *= corr1; o[nb][3] *= corr1;
        }

        // ---- O += P V (3-term split); P frags from S C-frags ----
        #pragma unroll
        for (int kj = 0; kj < 4; kj++) {
            uint32_t pah[4], pal[4];
            pah[0] = pack_split_hi(s[2*kj][0],   s[2*kj][1]);
            pal[0] = pack_split_lo(s[2*kj][0],   s[2*kj][1]);
            pah[1] = pack_split_hi(s[2*kj][2],   s[2*kj][3]);
            pal[1] = pack_split_lo(s[2*kj][2],   s[2*kj][3]);
            pah[2] = pack_split_hi(s[2*kj+1][0], s[2*kj+1][1]);
            pal[2] = pack_split_lo(s[2*kj+1][0], s[2*kj+1][1]);
            pah[3] = pack_split_hi(s[2*kj+1][2], s[2*kj+1][3]);
            pal[3] = pack_split_lo(s[2*kj+1][2], s[2*kj+1][3]);

            #pragma unroll
            for (int ep = 0; ep < 4; ep++) {
                uint32_t vh[4], vl[4];
                uint32_t voff = (uint32_t)(kj * 16 + ((mat & 1) << 3) + (lane & 7)) * APITCH
                              + (uint32_t)(((mat >> 1) << 4) + ep * 32);
                ldsm_x4_t(vh, bVh + voff);
                ldsm_x4_t(vl, bVl + voff);
                mma16816(o[ep*2],   pah, &vh[0]);
                mma16816(o[ep*2],   pah, &vl[0]);
                mma16816(o[ep*2],   pal, &vh[0]);
                mma16816(o[ep*2+1], pah, &vh[2]);
                mma16816(o[ep*2+1], pah, &vl[2]);
                mma16816(o[ep*2+1], pal, &vh[2]);
            }
        }

        if (ci + 2 < nch) {
            __syncthreads();            // all warps done reading slot ci&1
            issueKV(ci & 1, c + 128);
        }
    }

    // ---- normalize + split-store ----
    const float inv0 = 1.0f / l0, inv1 = 1.0f / l1;
    const size_t ob0 = (size_t)(b * L_ + gr0) * D_ + hoff;
    const size_t ob1 = (size_t)(b * L_ + gr1) * D_ + hoff;
    #pragma unroll
    for (int nb = 0; nb < 8; nb++) {
        int e = nb * 8 + (lane & 3) * 2;
        float v00 = o[nb][0] * inv0, v01 = o[nb][1] * inv0;
        float v10 = o[nb][2] * inv1, v11 = o[nb][3] * inv1;
        *(uint32_t*)&ath[ob0 + e] = pack_split_hi(v00, v01);
        *(uint32_t*)&atl[ob0 + e] = pack_split_lo(v00, v01);
        *(uint32_t*)&ath[ob1 + e] = pack_split_hi(v10, v11);
        *(uint32_t*)&atl[ob1 + e] = pack_split_lo(v10, v11);
    }
}

// ---------------------------------------------------------------------------
extern "C" void kernel_launch(void* const* d_in, const int* in_sizes, int n_in,
                              void* d_out, int out_size)
{
    const float* x      = (const float*)d_in[0];
    const float* w_qkv  = (const float*)d_in[1];
    const float* b_qkv  = (const float*)d_in[2];
    const float* w_proj = (const float*)d_in[3];
    const float* b_proj = (const float*)d_in[4];
    float* out = (float*)d_out;

    __nv_bfloat16 *xh, *xl, *wqh, *wql, *wph, *wpl, *qvh, *qvl, *ath, *atl;
    cudaGetSymbolAddress((void**)&xh,  g_xh);  cudaGetSymbolAddress((void**)&xl,  g_xl);
    cudaGetSymbolAddress((void**)&wqh, g_wqh); cudaGetSymbolAddress((void**)&wql, g_wql);
    cudaGetSymbolAddress((void**)&wph, g_wph); cudaGetSymbolAddress((void**)&wpl, g_wpl);
    cudaGetSymbolAddress((void**)&qvh, g_qvh); cudaGetSymbolAddress((void**)&qvl, g_qvl);
    cudaGetSymbolAddress((void**)&ath, g_ath); cudaGetSymbolAddress((void**)&atl, g_atl);

    cudaFuncSetAttribute(gemm_tc<true>,  cudaFuncAttributeMaxDynamicSharedMemorySize, SMEM_DYN);
    cudaFuncSetAttribute(gemm_tc<false>, cudaFuncAttributeMaxDynamicSharedMemorySize, SMEM_DYN);
    cudaFuncSetAttribute(attn_tc, cudaFuncAttributeMaxDynamicSharedMemorySize, ASMEM);

    // 0) one-time fp32 -> bf16 hi/lo splits
    split_kernel<<<(NT*D_/4 + 255)/256, 256>>>(x,      xh,  xl,  NT*D_/4);
    split_kernel<<<(N3*D_/4 + 255)/256, 256>>>(w_qkv,  wqh, wql, N3*D_/4);
    split_kernel<<<(D_*D_/4 + 255)/256, 256>>>(w_proj, wph, wpl, D_*D_/4);

    // 1) qkv = x @ w_qkv^T + b_qkv  -> bf16 hi/lo   [4096, 3072]
    gemm_tc<true><<<dim3(N3 / 128, NT / 128), 256, SMEM_DYN>>>(
        xh, xl, wqh, wql, b_qkv, nullptr, qvh, qvl, NT, N3, D_);

    // 2) tensor-core sliding-window attention -> bf16 hi/lo  [4096, 1024]
    attn_tc<<<dim3(L_ / 64, H_, B_), 128, ASMEM>>>(qvh, qvl, ath, atl);

    // 3) out = att @ w_proj^T + b_proj   [4096, 1024] fp32
    gemm_tc<false><<<dim3(D_ / 128, NT / 128), 256, SMEM_DYN>>>(
        ath, atl, wph, wpl, b_proj, out, nullptr, nullptr, NT, D_, D_);
}